// round 15
// baseline (speedup 1.0000x reference)
#include <cuda_runtime.h>
#include <cuda_fp16.h>
#include <math.h>
#include <stdint.h>

#define D     128
#define MAX_N 50048
#define MAX_E 800000
#define GEMM_BLKS 296

// ---- scratch: __device__ globals, device-side references only ----
__device__ float   g_h[MAX_N * D];      // gemm1 output h1 (fp32)
__device__ float   g_z[MAX_N];          // relu(agg1+b1) @ (W2@Wl)
__device__ float   g_dinv[MAX_N];
__device__ int     g_deg[MAX_N];        // zeroed at start + by zagg tail each replay
__device__ int     g_rowptr[MAX_N + 1];
__device__ int     g_cursor[MAX_N];
__device__ int2    g_csr[MAX_E];        // {src, float_bits(weight)}
__device__ float   g_v[D];              // W2 @ Wl
__device__ float   g_c;                 // b2.Wl + bl
__device__ int     g_bsum[256];
__device__ int     g_done;              // scan phase-A counter (reset by zagg)
__device__ int     g_flag;              // scan phase-B flag    (reset by zagg)

// ---- packed f32x2 helpers ----
#define FMA2(acc, v, w) \
    asm("fma.rn.f32x2 %0, %1, %2, %0;" : "+l"(acc) : "l"(v), "l"(w))
#define PACK2(out, lo, hi) \
    asm("mov.b64 %0, {%1, %2};" : "=l"(out) : "f"(lo), "f"(hi))
#define UNPACK2(lo, hi, in) \
    asm("mov.b64 {%0, %1}, %2;" : "=f"(lo), "=f"(hi) : "l"(in))

// ---- warp-local edge dtype probe: int64 ids < 50000 => odd words all 0 ----
__device__ __forceinline__ int probe_is32(const int* __restrict__ ei32) {
    int lane = threadIdx.x & 31;
    int nz = ei32[2 * lane + 1];
    return __ballot_sync(0xffffffffu, nz != 0) != 0u;
}

__device__ __forceinline__ int edge_ld(const void* ei, int is32, int idx) {
    return is32 ? ((const int*)ei)[idx]
                : (int)((const long long*)ei)[idx];
}

// ================= K0: degree count =================
__global__ void deg_count_kernel(const void* __restrict__ ei, int E) {
    int is32 = probe_is32((const int*)ei);
    int e = blockIdx.x * blockDim.x + threadIdx.x;
    if (e < E) atomicAdd(&g_deg[edge_ld(ei, is32, E + e)], 1);
}

// ========== K1: one-kernel parallel scan + dinv (196 blocks x 256) ========
__global__ void scan_dinv_kernel(int n) {
    __shared__ int wls[8];
    const int tid = threadIdx.x, b = blockIdx.x;
    const int lane = tid & 31, w = tid >> 5;
    const int i = b * 256 + tid;
    const int v = (i < n) ? g_deg[i] : 0;

    int x = v;
#pragma unroll
    for (int o = 1; o < 32; o <<= 1) {
        int t = __shfl_up_sync(0xffffffffu, x, o);
        if (lane >= o) x += t;
    }
    if (lane == 31) wls[w] = x;
    __syncthreads();
    if (w == 0) {
        int y = (lane < 8) ? wls[lane] : 0;
#pragma unroll
        for (int o = 1; o < 8; o <<= 1) {
            int t = __shfl_up_sync(0xffffffffu, y, o);
            if (lane >= o) y += t;
        }
        if (lane < 8) wls[lane] = y;
    }
    __syncthreads();
    int blk_excl = x - v + (w ? wls[w - 1] : 0);
    int blk_total = wls[7];

    if (tid == 0) {
        g_bsum[b] = blk_total;
        __threadfence();
        atomicAdd(&g_done, 1);
    }

    if (b == 0) {
        if (tid == 0) while (atomicAdd(&g_done, 0) < gridDim.x) { }
        __syncthreads();
        int nb = gridDim.x;
        int val = (tid < nb) ? g_bsum[tid] : 0;
        int xx = val;
#pragma unroll
        for (int o = 1; o < 32; o <<= 1) {
            int t = __shfl_up_sync(0xffffffffu, xx, o);
            if (lane >= o) xx += t;
        }
        if (lane == 31) wls[w] = xx;
        __syncthreads();
        if (w == 0) {
            int y = (lane < 8) ? wls[lane] : 0;
#pragma unroll
            for (int o = 1; o < 8; o <<= 1) {
                int t = __shfl_up_sync(0xffffffffu, y, o);
                if (lane >= o) y += t;
            }
            if (lane < 8) wls[lane] = y;
        }
        __syncthreads();
        int incl = xx + (w ? wls[w - 1] : 0);
        if (tid < nb) g_bsum[tid] = incl - val;
        __threadfence();
        __syncthreads();
        if (tid == 0) atomicExch(&g_flag, 1);
    }

    if (tid == 0) while (atomicAdd(&g_flag, 0) == 0) { }
    __syncthreads();
    __threadfence();

    int excl = g_bsum[b] + blk_excl;
    if (i < n) {
        g_rowptr[i] = excl;
        g_cursor[i] = excl;
        g_dinv[i] = rsqrtf((float)(v + 1));
        if (i == n - 1) g_rowptr[n] = excl + v;
    }
}

// ===== K2 mega: [0,296) gemm1 | [296,296+nbE) csr_fill | last: wv ========
__global__ __launch_bounds__(256, 2) void mega_kernel(
    const float* __restrict__ A, const float* __restrict__ W,
    const void* __restrict__ ei,
    const float* __restrict__ W2, const float* __restrict__ b2,
    const float* __restrict__ Wl, const float* __restrict__ bl,
    int n, int E, int nbE)
{
    __shared__ uint32_t As[64][132];

    const int tid = threadIdx.x;

    if (blockIdx.x < GEMM_BLKS) {
        const int wid = tid >> 5, lane = tid & 31;
        const int group = lane >> 2, four = lane & 3;

        uint32_t breg[2][16][2];
#pragma unroll
        for (int nt = 0; nt < 2; nt++) {
            int ncol = wid * 16 + nt * 8 + group;
#pragma unroll
            for (int k = 0; k < 16; k++) {
                float w0 = __ldg(&W[(k * 8 + four) * D + ncol]);
                float w1 = __ldg(&W[(k * 8 + four + 4) * D + ncol]);
                asm("cvt.rna.tf32.f32 %0, %1;" : "=r"(breg[nt][k][0]) : "f"(w0));
                asm("cvt.rna.tf32.f32 %0, %1;" : "=r"(breg[nt][k][1]) : "f"(w1));
            }
        }

        const int nTiles = (n + 63) >> 6;
        for (int tile = blockIdx.x; tile < nTiles; tile += GEMM_BLKS) {
            const int rowBase = tile * 64;

            for (int i = tid; i < 64 * 32; i += 256) {
                int r = i >> 5, c4 = i & 31;
                int row = rowBase + r;
                float4 v = (row < n) ? ((const float4*)(A + (size_t)row * D))[c4]
                                     : make_float4(0.f, 0.f, 0.f, 0.f);
                uint32_t t0, t1, t2, t3;
                asm("cvt.rna.tf32.f32 %0, %1;" : "=r"(t0) : "f"(v.x));
                asm("cvt.rna.tf32.f32 %0, %1;" : "=r"(t1) : "f"(v.y));
                asm("cvt.rna.tf32.f32 %0, %1;" : "=r"(t2) : "f"(v.z));
                asm("cvt.rna.tf32.f32 %0, %1;" : "=r"(t3) : "f"(v.w));
                As[r][c4 * 4 + 0] = t0;
                As[r][c4 * 4 + 1] = t1;
                As[r][c4 * 4 + 2] = t2;
                As[r][c4 * 4 + 3] = t3;
            }
            __syncthreads();

            float acc[4][2][4];
#pragma unroll
            for (int ms = 0; ms < 4; ms++)
#pragma unroll
                for (int nt = 0; nt < 2; nt++)
#pragma unroll
                    for (int c = 0; c < 4; c++) acc[ms][nt][c] = 0.f;

#pragma unroll
            for (int ms = 0; ms < 4; ms++) {
                const int r0 = ms * 16 + group;
#pragma unroll
                for (int k = 0; k < 16; k++) {
                    const int k0 = k * 8;
                    uint32_t a0 = As[r0][k0 + four];
                    uint32_t a1 = As[r0 + 8][k0 + four];
                    uint32_t a2 = As[r0][k0 + four + 4];
                    uint32_t a3 = As[r0 + 8][k0 + four + 4];
#pragma unroll
                    for (int nt = 0; nt < 2; nt++) {
                        asm volatile(
                            "mma.sync.aligned.m16n8k8.row.col.f32.tf32.tf32.f32 "
                            "{%0,%1,%2,%3}, {%4,%5,%6,%7}, {%8,%9}, {%0,%1,%2,%3};"
                            : "+f"(acc[ms][nt][0]), "+f"(acc[ms][nt][1]),
                              "+f"(acc[ms][nt][2]), "+f"(acc[ms][nt][3])
                            : "r"(a0), "r"(a1), "r"(a2), "r"(a3),
                              "r"(breg[nt][k][0]), "r"(breg[nt][k][1]));
                    }
                }
            }

#pragma unroll
            for (int ms = 0; ms < 4; ms++) {
                int row0 = rowBase + ms * 16 + group;
#pragma unroll
                for (int nt = 0; nt < 2; nt++) {
                    int col = wid * 16 + nt * 8 + four * 2;
                    if (row0 < n)
                        *(float2*)&g_h[(size_t)row0 * D + col] =
                            make_float2(acc[ms][nt][0], acc[ms][nt][1]);
                    if (row0 + 8 < n)
                        *(float2*)&g_h[(size_t)(row0 + 8) * D + col] =
                            make_float2(acc[ms][nt][2], acc[ms][nt][3]);
                }
            }
            __syncthreads();
        }
    } else if (blockIdx.x < GEMM_BLKS + nbE) {
        int is32 = probe_is32((const int*)ei);
        int e = (blockIdx.x - GEMM_BLKS) * 256 + tid;
        if (e < E) {
            int s = edge_ld(ei, is32, e);
            int d = edge_ld(ei, is32, E + e);
            int pos = atomicAdd(&g_cursor[d], 1);
            float w = g_dinv[s] * g_dinv[d];
            g_csr[pos] = make_int2(s, __float_as_int(w));
        }
    } else {
        // head precompute; all 256 threads reach barriers, work gated tid<128
        __shared__ float wl[D];
        __shared__ float cpart[D];
        int k = tid;
        if (k < D) wl[k] = Wl[k];
        __syncthreads();
        if (k < D) {
            float s = 0.f;
#pragma unroll 8
            for (int j = 0; j < D; j++) s += W2[k * D + j] * wl[j];
            g_v[k] = s;
            cpart[k] = b2[k] * wl[k];
        }
        __syncthreads();
        for (int st = 64; st; st >>= 1) {
            if (k < st) cpart[k] += cpart[k + st];
            __syncthreads();
        }
        if (k == 0) g_c = cpart[0] + bl[0];
    }
}

// ==== K3 (profiled): layer-1 agg (warp/row, f32x2 FMA) + bias+relu+z =====
__global__ void agg_bias_relu_z_kernel(const float* __restrict__ b, int n)
{
    int gt = blockIdx.x * blockDim.x + threadIdx.x;
    int row = gt >> 5, lane = gt & 31;
    if (row >= n) return;

    const ulonglong2* h2 = (const ulonglong2*)g_h;   // 16B = 2 packed f32x2

    float di = g_dinv[row];
    float w0 = di * di;
    unsigned long long acc01, acc23, ww;
    PACK2(acc01, 0.f, 0.f);
    acc23 = acc01;
    PACK2(ww, w0, w0);
    {
        ulonglong2 u = h2[row * 32 + lane];
        FMA2(acc01, u.x, ww);
        FMA2(acc23, u.y, ww);
    }

    int end = g_rowptr[row + 1];
    int e = g_rowptr[row];
    for (; e + 7 < end; e += 8) {
        int2 p[8];
#pragma unroll
        for (int j = 0; j < 8; j++) p[j] = g_csr[e + j];
        ulonglong2 u[8];
#pragma unroll
        for (int j = 0; j < 8; j++) u[j] = h2[p[j].x * 32 + lane];
#pragma unroll
        for (int j = 0; j < 8; j++) {
            float w = __int_as_float(p[j].y);
            unsigned long long wp;
            PACK2(wp, w, w);
            FMA2(acc01, u[j].x, wp);
            FMA2(acc23, u[j].y, wp);
        }
    }
    for (; e < end; e++) {
        int2 p = g_csr[e];
        float w = __int_as_float(p.y);
        unsigned long long wp;
        PACK2(wp, w, w);
        ulonglong2 u = h2[p.x * 32 + lane];
        FMA2(acc01, u.x, wp);
        FMA2(acc23, u.y, wp);
    }

    float a0, a1, a2, a3;
    UNPACK2(a0, a1, acc01);
    UNPACK2(a2, a3, acc23);

    float4 bb = ((const float4*)b)[lane];
    a0 = fmaxf(a0 + bb.x, 0.f);
    a1 = fmaxf(a1 + bb.y, 0.f);
    a2 = fmaxf(a2 + bb.z, 0.f);
    a3 = fmaxf(a3 + bb.w, 0.f);

    float4 vv = ((const float4*)g_v)[lane];
    float s = a0 * vv.x + a1 * vv.y + a2 * vv.z + a3 * vv.w;
#pragma unroll
    for (int o = 16; o; o >>= 1) s += __shfl_xor_sync(0xffffffffu, s, o);
    if (lane == 0) g_z[row] = s;
}

// ==== K4: collapsed layer 2 + head; tail resets scratch for next replay ==
__global__ void zagg_kernel(float* __restrict__ out, int n)
{
    int i = blockIdx.x * blockDim.x + threadIdx.x;
    if (i >= n) return;
    g_deg[i] = 0;
    if (i == 0) { g_done = 0; g_flag = 0; }
    float di = g_dinv[i];
    float acc = di * di * g_z[i];
    int end = g_rowptr[i + 1];
    int e = g_rowptr[i];
    for (; e + 7 < end; e += 8) {
        int2 p[8];
#pragma unroll
        for (int j = 0; j < 8; j++) p[j] = g_csr[e + j];
        float zz[8];
#pragma unroll
        for (int j = 0; j < 8; j++) zz[j] = g_z[p[j].x];
#pragma unroll
        for (int j = 0; j < 8; j++)
            acc += __int_as_float(p[j].y) * zz[j];
    }
    for (; e < end; e++) {
        int2 p = g_csr[e];
        acc += __int_as_float(p.y) * g_z[p.x];
    }
    out[i] = 1.f / (1.f + expf(-(acc + g_c)));
}

// ================= host =================
extern "C" void kernel_launch(void* const* d_in, const int* in_sizes, int n_in,
                              void* d_out, int out_size)
{
    const float* x  = (const float*)d_in[0];
    const void*  ei = d_in[1];
    const float* W1 = (const float*)d_in[2];
    const float* b1 = (const float*)d_in[3];
    const float* W2 = (const float*)d_in[4];
    const float* b2 = (const float*)d_in[5];
    const float* Wl = (const float*)d_in[6];
    const float* bl = (const float*)d_in[7];
    float* out = (float*)d_out;

    const int n = in_sizes[0] / D;   // 50000
    const int E = in_sizes[1] / 2;   // 800000

    const int TB = 256;
    int nb_n     = (n + TB - 1) / TB;        // 196
    int nb_E     = (E + TB - 1) / TB;        // 3125
    int nb_warpN = (n * 32 + TB - 1) / TB;   // 6250

    deg_count_kernel<<<nb_E, TB>>>(ei, E);                           // 0
    scan_dinv_kernel<<<nb_n, TB>>>(n);                               // 1
    mega_kernel<<<GEMM_BLKS + nb_E + 1, TB>>>(x, W1, ei,
                                              W2, b2, Wl, bl,
                                              n, E, nb_E);           // 2
    agg_bias_relu_z_kernel<<<nb_warpN, TB>>>(b1, n);                 // 3 <- profiled
    zagg_kernel<<<nb_n, TB>>>(out, n);                               // 4
}

// round 16
// speedup vs baseline: 1.1561x; 1.1561x over previous
#include <cuda_runtime.h>
#include <cuda_fp16.h>
#include <math.h>
#include <stdint.h>

#define D     128
#define MAX_N 50048
#define MAX_E 800000
#define GEMM_BLKS 296

// ---- scratch: __device__ globals, device-side references only ----
__device__ __half2 g_h16[MAX_N * 64];   // h' = dinv * (x@W1), fp16
__device__ float   g_z[MAX_N];          // z' = dinv * (relu(agg1+b1) . v)
__device__ float   g_dinv[MAX_N];
__device__ int     g_deg[MAX_N];        // zeroed at start + by zagg tail each replay
__device__ int     g_rowptr[MAX_N + 1];
__device__ int     g_cursor[MAX_N];
__device__ int     g_csr_src[MAX_E];    // weight-free CSR: src only
__device__ float   g_v[D];              // W2 @ Wl
__device__ float   g_c;                 // b2.Wl + bl
__device__ int     g_bsum[256];
__device__ int     g_done;              // scan phase-A counter (reset by zagg)
__device__ int     g_flag;              // scan phase-B flag    (reset by zagg)

// ---- warp-local edge dtype probe: int64 ids < 50000 => odd words all 0 ----
__device__ __forceinline__ int probe_is32(const int* __restrict__ ei32) {
    int lane = threadIdx.x & 31;
    int nz = ei32[2 * lane + 1];
    return __ballot_sync(0xffffffffu, nz != 0) != 0u;
}

__device__ __forceinline__ int edge_ld(const void* ei, int is32, int idx) {
    return is32 ? ((const int*)ei)[idx]
                : (int)((const long long*)ei)[idx];
}

// ================= K0: degree count =================
__global__ void deg_count_kernel(const void* __restrict__ ei, int E) {
    int is32 = probe_is32((const int*)ei);
    int e = blockIdx.x * blockDim.x + threadIdx.x;
    if (e < E) atomicAdd(&g_deg[edge_ld(ei, is32, E + e)], 1);
}

// ========== K1: one-kernel parallel scan + dinv (196 blocks x 256) ========
__global__ void scan_dinv_kernel(int n) {
    __shared__ int wls[8];
    const int tid = threadIdx.x, b = blockIdx.x;
    const int lane = tid & 31, w = tid >> 5;
    const int i = b * 256 + tid;
    const int v = (i < n) ? g_deg[i] : 0;

    int x = v;
#pragma unroll
    for (int o = 1; o < 32; o <<= 1) {
        int t = __shfl_up_sync(0xffffffffu, x, o);
        if (lane >= o) x += t;
    }
    if (lane == 31) wls[w] = x;
    __syncthreads();
    if (w == 0) {
        int y = (lane < 8) ? wls[lane] : 0;
#pragma unroll
        for (int o = 1; o < 8; o <<= 1) {
            int t = __shfl_up_sync(0xffffffffu, y, o);
            if (lane >= o) y += t;
        }
        if (lane < 8) wls[lane] = y;
    }
    __syncthreads();
    int blk_excl = x - v + (w ? wls[w - 1] : 0);
    int blk_total = wls[7];

    if (tid == 0) {
        g_bsum[b] = blk_total;
        __threadfence();
        atomicAdd(&g_done, 1);
    }

    if (b == 0) {
        if (tid == 0) while (atomicAdd(&g_done, 0) < gridDim.x) { }
        __syncthreads();
        int nb = gridDim.x;
        int val = (tid < nb) ? g_bsum[tid] : 0;
        int xx = val;
#pragma unroll
        for (int o = 1; o < 32; o <<= 1) {
            int t = __shfl_up_sync(0xffffffffu, xx, o);
            if (lane >= o) xx += t;
        }
        if (lane == 31) wls[w] = xx;
        __syncthreads();
        if (w == 0) {
            int y = (lane < 8) ? wls[lane] : 0;
#pragma unroll
            for (int o = 1; o < 8; o <<= 1) {
                int t = __shfl_up_sync(0xffffffffu, y, o);
                if (lane >= o) y += t;
            }
            if (lane < 8) wls[lane] = y;
        }
        __syncthreads();
        int incl = xx + (w ? wls[w - 1] : 0);
        if (tid < nb) g_bsum[tid] = incl - val;
        __threadfence();
        __syncthreads();
        if (tid == 0) atomicExch(&g_flag, 1);
    }

    if (tid == 0) while (atomicAdd(&g_flag, 0) == 0) { }
    __syncthreads();
    __threadfence();

    int excl = g_bsum[b] + blk_excl;
    if (i < n) {
        g_rowptr[i] = excl;
        g_cursor[i] = excl;
        g_dinv[i] = rsqrtf((float)(v + 1));
        if (i == n - 1) g_rowptr[n] = excl + v;
    }
}

// ===== K2 mega: [0,296) gemm1 (h'=dinv*x@W1) | csr_fill | wv ============
__global__ __launch_bounds__(256, 2) void mega_kernel(
    const float* __restrict__ A, const float* __restrict__ W,
    const void* __restrict__ ei,
    const float* __restrict__ W2, const float* __restrict__ b2,
    const float* __restrict__ Wl, const float* __restrict__ bl,
    int n, int E, int nbE)
{
    __shared__ uint32_t As[64][132];

    const int tid = threadIdx.x;

    if (blockIdx.x < GEMM_BLKS) {
        const int wid = tid >> 5, lane = tid & 31;
        const int group = lane >> 2, four = lane & 3;

        uint32_t breg[2][16][2];
#pragma unroll
        for (int nt = 0; nt < 2; nt++) {
            int ncol = wid * 16 + nt * 8 + group;
#pragma unroll
            for (int k = 0; k < 16; k++) {
                float w0 = __ldg(&W[(k * 8 + four) * D + ncol]);
                float w1 = __ldg(&W[(k * 8 + four + 4) * D + ncol]);
                asm("cvt.rna.tf32.f32 %0, %1;" : "=r"(breg[nt][k][0]) : "f"(w0));
                asm("cvt.rna.tf32.f32 %0, %1;" : "=r"(breg[nt][k][1]) : "f"(w1));
            }
        }

        const int nTiles = (n + 63) >> 6;
        for (int tile = blockIdx.x; tile < nTiles; tile += GEMM_BLKS) {
            const int rowBase = tile * 64;

            for (int i = tid; i < 64 * 32; i += 256) {
                int r = i >> 5, c4 = i & 31;
                int row = rowBase + r;
                float4 v = (row < n) ? ((const float4*)(A + (size_t)row * D))[c4]
                                     : make_float4(0.f, 0.f, 0.f, 0.f);
                uint32_t t0, t1, t2, t3;
                asm("cvt.rna.tf32.f32 %0, %1;" : "=r"(t0) : "f"(v.x));
                asm("cvt.rna.tf32.f32 %0, %1;" : "=r"(t1) : "f"(v.y));
                asm("cvt.rna.tf32.f32 %0, %1;" : "=r"(t2) : "f"(v.z));
                asm("cvt.rna.tf32.f32 %0, %1;" : "=r"(t3) : "f"(v.w));
                As[r][c4 * 4 + 0] = t0;
                As[r][c4 * 4 + 1] = t1;
                As[r][c4 * 4 + 2] = t2;
                As[r][c4 * 4 + 3] = t3;
            }
            __syncthreads();

            float acc[4][2][4];
#pragma unroll
            for (int ms = 0; ms < 4; ms++)
#pragma unroll
                for (int nt = 0; nt < 2; nt++)
#pragma unroll
                    for (int c = 0; c < 4; c++) acc[ms][nt][c] = 0.f;

#pragma unroll
            for (int ms = 0; ms < 4; ms++) {
                const int r0 = ms * 16 + group;
#pragma unroll
                for (int k = 0; k < 16; k++) {
                    const int k0 = k * 8;
                    uint32_t a0 = As[r0][k0 + four];
                    uint32_t a1 = As[r0 + 8][k0 + four];
                    uint32_t a2 = As[r0][k0 + four + 4];
                    uint32_t a3 = As[r0 + 8][k0 + four + 4];
#pragma unroll
                    for (int nt = 0; nt < 2; nt++) {
                        asm volatile(
                            "mma.sync.aligned.m16n8k8.row.col.f32.tf32.tf32.f32 "
                            "{%0,%1,%2,%3}, {%4,%5,%6,%7}, {%8,%9}, {%0,%1,%2,%3};"
                            : "+f"(acc[ms][nt][0]), "+f"(acc[ms][nt][1]),
                              "+f"(acc[ms][nt][2]), "+f"(acc[ms][nt][3])
                            : "r"(a0), "r"(a1), "r"(a2), "r"(a3),
                              "r"(breg[nt][k][0]), "r"(breg[nt][k][1]));
                    }
                }
            }

            // epilogue: scale by dinv[row], store fp16 h'
#pragma unroll
            for (int ms = 0; ms < 4; ms++) {
                int row0 = rowBase + ms * 16 + group;
                float d0 = (row0 < n) ? __ldg(&g_dinv[row0]) : 0.f;
                float d1 = (row0 + 8 < n) ? __ldg(&g_dinv[row0 + 8]) : 0.f;
#pragma unroll
                for (int nt = 0; nt < 2; nt++) {
                    int colh = (wid * 16 + nt * 8 + four * 2) >> 1;
                    if (row0 < n)
                        g_h16[(size_t)row0 * 64 + colh] =
                            __floats2half2_rn(acc[ms][nt][0] * d0,
                                              acc[ms][nt][1] * d0);
                    if (row0 + 8 < n)
                        g_h16[(size_t)(row0 + 8) * 64 + colh] =
                            __floats2half2_rn(acc[ms][nt][2] * d1,
                                              acc[ms][nt][3] * d1);
                }
            }
            __syncthreads();
        }
    } else if (blockIdx.x < GEMM_BLKS + nbE) {
        // weight-free CSR fill: src index only
        int is32 = probe_is32((const int*)ei);
        int e = (blockIdx.x - GEMM_BLKS) * 256 + tid;
        if (e < E) {
            int s = edge_ld(ei, is32, e);
            int d = edge_ld(ei, is32, E + e);
            int pos = atomicAdd(&g_cursor[d], 1);
            g_csr_src[pos] = s;
        }
    } else {
        // head precompute; all 256 threads reach barriers, work gated tid<128
        __shared__ float wl[D];
        __shared__ float cpart[D];
        int k = tid;
        if (k < D) wl[k] = Wl[k];
        __syncthreads();
        if (k < D) {
            float s = 0.f;
#pragma unroll 8
            for (int j = 0; j < D; j++) s += W2[k * D + j] * wl[j];
            g_v[k] = s;
            cpart[k] = b2[k] * wl[k];
        }
        __syncthreads();
        for (int st = 64; st; st >>= 1) {
            if (k < st) cpart[k] += cpart[k + st];
            __syncthreads();
        }
        if (k == 0) g_c = cpart[0] + bl[0];
    }
}

// ---- fp16 row fragment load: cols [4*lane, 4*lane+4) ----
__device__ __forceinline__ float4 ld_row16(int row, int lane) {
    uint2 u = *(const uint2*)(g_h16 + (size_t)row * 64 + lane * 2);
    __half2 h0 = *(__half2*)&u.x;
    __half2 h1 = *(__half2*)&u.y;
    float2 f0 = __half22float2(h0);
    float2 f1 = __half22float2(h1);
    return make_float4(f0.x, f0.y, f1.x, f1.y);
}

// ==== K3 (profiled): agg1 = dinv*(h'self + sum h'src); +b1, relu, z' ====
__global__ void agg_bias_relu_z_kernel(const float* __restrict__ b, int n)
{
    int gt = blockIdx.x * blockDim.x + threadIdx.x;
    int row = gt >> 5, lane = gt & 31;
    if (row >= n) return;

    float4 acc = ld_row16(row, lane);          // self h'

    int end = g_rowptr[row + 1];
    int e = g_rowptr[row];
    for (; e + 7 < end; e += 8) {
        int s[8];
#pragma unroll
        for (int j = 0; j < 8; j++) s[j] = __ldg(&g_csr_src[e + j]);
        float4 v[8];
#pragma unroll
        for (int j = 0; j < 8; j++) v[j] = ld_row16(s[j], lane);
#pragma unroll
        for (int j = 0; j < 8; j++) {
            acc.x += v[j].x;
            acc.y += v[j].y;
            acc.z += v[j].z;
            acc.w += v[j].w;
        }
    }
    for (; e < end; e++) {
        float4 v0 = ld_row16(__ldg(&g_csr_src[e]), lane);
        acc.x += v0.x; acc.y += v0.y;
        acc.z += v0.z; acc.w += v0.w;
    }

    float di = g_dinv[row];
    float4 bb = ((const float4*)b)[lane];
    float a0 = fmaxf(acc.x * di + bb.x, 0.f);
    float a1 = fmaxf(acc.y * di + bb.y, 0.f);
    float a2 = fmaxf(acc.z * di + bb.z, 0.f);
    float a3 = fmaxf(acc.w * di + bb.w, 0.f);

    float4 vv = ((const float4*)g_v)[lane];
    float s = a0 * vv.x + a1 * vv.y + a2 * vv.z + a3 * vv.w;
#pragma unroll
    for (int o = 16; o; o >>= 1) s += __shfl_xor_sync(0xffffffffu, s, o);
    if (lane == 0) g_z[row] = di * s;          // store z' = dinv * z
}

// ==== K4: out = sigmoid(dinv*(z'self + sum z'src) + c); resets scratch ===
__global__ void zagg_kernel(float* __restrict__ out, int n)
{
    int i = blockIdx.x * blockDim.x + threadIdx.x;
    if (i >= n) return;
    g_deg[i] = 0;
    if (i == 0) { g_done = 0; g_flag = 0; }
    float acc = g_z[i];
    int end = g_rowptr[i + 1];
    int e = g_rowptr[i];
    for (; e + 7 < end; e += 8) {
        int s[8];
#pragma unroll
        for (int j = 0; j < 8; j++) s[j] = __ldg(&g_csr_src[e + j]);
        float zz[8];
#pragma unroll
        for (int j = 0; j < 8; j++) zz[j] = g_z[s[j]];
#pragma unroll
        for (int j = 0; j < 8; j++) acc += zz[j];
    }
    for (; e < end; e++)
        acc += g_z[__ldg(&g_csr_src[e])];
    out[i] = 1.f / (1.f + expf(-(g_dinv[i] * acc + g_c)));
}

// ================= host =================
extern "C" void kernel_launch(void* const* d_in, const int* in_sizes, int n_in,
                              void* d_out, int out_size)
{
    const float* x  = (const float*)d_in[0];
    const void*  ei = d_in[1];
    const float* W1 = (const float*)d_in[2];
    const float* b1 = (const float*)d_in[3];
    const float* W2 = (const float*)d_in[4];
    const float* b2 = (const float*)d_in[5];
    const float* Wl = (const float*)d_in[6];
    const float* bl = (const float*)d_in[7];
    float* out = (float*)d_out;

    const int n = in_sizes[0] / D;   // 50000
    const int E = in_sizes[1] / 2;   // 800000

    const int TB = 256;
    int nb_n     = (n + TB - 1) / TB;        // 196
    int nb_E     = (E + TB - 1) / TB;        // 3125
    int nb_warpN = (n * 32 + TB - 1) / TB;   // 6250

    deg_count_kernel<<<nb_E, TB>>>(ei, E);                           // 0
    scan_dinv_kernel<<<nb_n, TB>>>(n);                               // 1
    mega_kernel<<<GEMM_BLKS + nb_E + 1, TB>>>(x, W1, ei,
                                              W2, b2, Wl, bl,
                                              n, E, nb_E);           // 2
    agg_bias_relu_z_kernel<<<nb_warpN, TB>>>(b1, n);                 // 3 <- profiled
    zagg_kernel<<<nb_n, TB>>>(out, n);                               // 4
}

// round 17
// speedup vs baseline: 1.1863x; 1.0261x over previous
#include <cuda_runtime.h>
#include <cuda_fp16.h>
#include <math.h>
#include <stdint.h>

#define D     128
#define MAX_N 50048
#define MAX_E 800000
#define GEMM_BLKS 296

// ---- scratch: __device__ globals, device-side references only ----
__device__ __half2 g_h16[MAX_N * 64];   // h' = dinv * (x@W1), fp16
__device__ float   g_z[MAX_N];          // z' = dinv * (relu(agg1+b1) . v)
__device__ float   g_dinv[MAX_N];
__device__ int     g_deg[MAX_N];        // zeroed at start + by zagg tail each replay
__device__ int     g_rowptr[MAX_N + 1];
__device__ int     g_cursor[MAX_N];
__device__ int     g_csr_src[MAX_E];    // weight-free CSR: src only
__device__ float   g_v[D];              // W2 @ Wl
__device__ float   g_c;                 // b2.Wl + bl
__device__ int     g_bsum[256];
__device__ int     g_done;              // scan phase-A counter (reset by zagg)
__device__ int     g_flag;              // scan phase-B flag    (reset by zagg)

// ---- warp-local edge dtype probe: int64 ids < 50000 => odd words all 0 ----
__device__ __forceinline__ int probe_is32(const int* __restrict__ ei32) {
    int lane = threadIdx.x & 31;
    int nz = ei32[2 * lane + 1];
    return __ballot_sync(0xffffffffu, nz != 0) != 0u;
}

__device__ __forceinline__ int edge_ld(const void* ei, int is32, int idx) {
    return is32 ? ((const int*)ei)[idx]
                : (int)((const long long*)ei)[idx];
}

// ================= K0: degree count =================
__global__ void deg_count_kernel(const void* __restrict__ ei, int E) {
    int is32 = probe_is32((const int*)ei);
    int e = blockIdx.x * blockDim.x + threadIdx.x;
    if (e < E) atomicAdd(&g_deg[edge_ld(ei, is32, E + e)], 1);
}

// ========== K1: one-kernel parallel scan + dinv (196 blocks x 256) ========
__global__ void scan_dinv_kernel(int n) {
    __shared__ int wls[8];
    const int tid = threadIdx.x, b = blockIdx.x;
    const int lane = tid & 31, w = tid >> 5;
    const int i = b * 256 + tid;
    const int v = (i < n) ? g_deg[i] : 0;

    int x = v;
#pragma unroll
    for (int o = 1; o < 32; o <<= 1) {
        int t = __shfl_up_sync(0xffffffffu, x, o);
        if (lane >= o) x += t;
    }
    if (lane == 31) wls[w] = x;
    __syncthreads();
    if (w == 0) {
        int y = (lane < 8) ? wls[lane] : 0;
#pragma unroll
        for (int o = 1; o < 8; o <<= 1) {
            int t = __shfl_up_sync(0xffffffffu, y, o);
            if (lane >= o) y += t;
        }
        if (lane < 8) wls[lane] = y;
    }
    __syncthreads();
    int blk_excl = x - v + (w ? wls[w - 1] : 0);
    int blk_total = wls[7];

    if (tid == 0) {
        g_bsum[b] = blk_total;
        __threadfence();
        atomicAdd(&g_done, 1);
    }

    if (b == 0) {
        if (tid == 0) while (atomicAdd(&g_done, 0) < gridDim.x) { }
        __syncthreads();
        int nb = gridDim.x;
        int val = (tid < nb) ? g_bsum[tid] : 0;
        int xx = val;
#pragma unroll
        for (int o = 1; o < 32; o <<= 1) {
            int t = __shfl_up_sync(0xffffffffu, xx, o);
            if (lane >= o) xx += t;
        }
        if (lane == 31) wls[w] = xx;
        __syncthreads();
        if (w == 0) {
            int y = (lane < 8) ? wls[lane] : 0;
#pragma unroll
            for (int o = 1; o < 8; o <<= 1) {
                int t = __shfl_up_sync(0xffffffffu, y, o);
                if (lane >= o) y += t;
            }
            if (lane < 8) wls[lane] = y;
        }
        __syncthreads();
        int incl = xx + (w ? wls[w - 1] : 0);
        if (tid < nb) g_bsum[tid] = incl - val;
        __threadfence();
        __syncthreads();
        if (tid == 0) atomicExch(&g_flag, 1);
    }

    if (tid == 0) while (atomicAdd(&g_flag, 0) == 0) { }
    __syncthreads();
    __threadfence();

    int excl = g_bsum[b] + blk_excl;
    if (i < n) {
        g_rowptr[i] = excl;
        g_cursor[i] = excl;
        g_dinv[i] = rsqrtf((float)(v + 1));
        if (i == n - 1) g_rowptr[n] = excl + v;
    }
}

// ===== K2 mega: [0,296) gemm1 (h'=dinv*x@W1) | csr_fill | wv ============
__global__ __launch_bounds__(256, 2) void mega_kernel(
    const float* __restrict__ A, const float* __restrict__ W,
    const void* __restrict__ ei,
    const float* __restrict__ W2, const float* __restrict__ b2,
    const float* __restrict__ Wl, const float* __restrict__ bl,
    int n, int E, int nbE)
{
    __shared__ uint32_t As[64][132];

    const int tid = threadIdx.x;

    if (blockIdx.x < GEMM_BLKS) {
        const int wid = tid >> 5, lane = tid & 31;
        const int group = lane >> 2, four = lane & 3;

        uint32_t breg[2][16][2];
#pragma unroll
        for (int nt = 0; nt < 2; nt++) {
            int ncol = wid * 16 + nt * 8 + group;
#pragma unroll
            for (int k = 0; k < 16; k++) {
                float w0 = __ldg(&W[(k * 8 + four) * D + ncol]);
                float w1 = __ldg(&W[(k * 8 + four + 4) * D + ncol]);
                asm("cvt.rna.tf32.f32 %0, %1;" : "=r"(breg[nt][k][0]) : "f"(w0));
                asm("cvt.rna.tf32.f32 %0, %1;" : "=r"(breg[nt][k][1]) : "f"(w1));
            }
        }

        const int nTiles = (n + 63) >> 6;
        for (int tile = blockIdx.x; tile < nTiles; tile += GEMM_BLKS) {
            const int rowBase = tile * 64;

            for (int i = tid; i < 64 * 32; i += 256) {
                int r = i >> 5, c4 = i & 31;
                int row = rowBase + r;
                float4 v = (row < n) ? ((const float4*)(A + (size_t)row * D))[c4]
                                     : make_float4(0.f, 0.f, 0.f, 0.f);
                uint32_t t0, t1, t2, t3;
                asm("cvt.rna.tf32.f32 %0, %1;" : "=r"(t0) : "f"(v.x));
                asm("cvt.rna.tf32.f32 %0, %1;" : "=r"(t1) : "f"(v.y));
                asm("cvt.rna.tf32.f32 %0, %1;" : "=r"(t2) : "f"(v.z));
                asm("cvt.rna.tf32.f32 %0, %1;" : "=r"(t3) : "f"(v.w));
                As[r][c4 * 4 + 0] = t0;
                As[r][c4 * 4 + 1] = t1;
                As[r][c4 * 4 + 2] = t2;
                As[r][c4 * 4 + 3] = t3;
            }
            __syncthreads();

            float acc[4][2][4];
#pragma unroll
            for (int ms = 0; ms < 4; ms++)
#pragma unroll
                for (int nt = 0; nt < 2; nt++)
#pragma unroll
                    for (int c = 0; c < 4; c++) acc[ms][nt][c] = 0.f;

#pragma unroll
            for (int ms = 0; ms < 4; ms++) {
                const int r0 = ms * 16 + group;
#pragma unroll
                for (int k = 0; k < 16; k++) {
                    const int k0 = k * 8;
                    uint32_t a0 = As[r0][k0 + four];
                    uint32_t a1 = As[r0 + 8][k0 + four];
                    uint32_t a2 = As[r0][k0 + four + 4];
                    uint32_t a3 = As[r0 + 8][k0 + four + 4];
#pragma unroll
                    for (int nt = 0; nt < 2; nt++) {
                        asm volatile(
                            "mma.sync.aligned.m16n8k8.row.col.f32.tf32.tf32.f32 "
                            "{%0,%1,%2,%3}, {%4,%5,%6,%7}, {%8,%9}, {%0,%1,%2,%3};"
                            : "+f"(acc[ms][nt][0]), "+f"(acc[ms][nt][1]),
                              "+f"(acc[ms][nt][2]), "+f"(acc[ms][nt][3])
                            : "r"(a0), "r"(a1), "r"(a2), "r"(a3),
                              "r"(breg[nt][k][0]), "r"(breg[nt][k][1]));
                    }
                }
            }

            // epilogue: scale by dinv[row], store fp16 h'
#pragma unroll
            for (int ms = 0; ms < 4; ms++) {
                int row0 = rowBase + ms * 16 + group;
                float d0 = (row0 < n) ? __ldg(&g_dinv[row0]) : 0.f;
                float d1 = (row0 + 8 < n) ? __ldg(&g_dinv[row0 + 8]) : 0.f;
#pragma unroll
                for (int nt = 0; nt < 2; nt++) {
                    int colh = (wid * 16 + nt * 8 + four * 2) >> 1;
                    if (row0 < n)
                        g_h16[(size_t)row0 * 64 + colh] =
                            __floats2half2_rn(acc[ms][nt][0] * d0,
                                              acc[ms][nt][1] * d0);
                    if (row0 + 8 < n)
                        g_h16[(size_t)(row0 + 8) * 64 + colh] =
                            __floats2half2_rn(acc[ms][nt][2] * d1,
                                              acc[ms][nt][3] * d1);
                }
            }
            __syncthreads();
        }
    } else if (blockIdx.x < GEMM_BLKS + nbE) {
        // weight-free CSR fill: src index only
        int is32 = probe_is32((const int*)ei);
        int e = (blockIdx.x - GEMM_BLKS) * 256 + tid;
        if (e < E) {
            int s = edge_ld(ei, is32, e);
            int d = edge_ld(ei, is32, E + e);
            int pos = atomicAdd(&g_cursor[d], 1);
            g_csr_src[pos] = s;
        }
    } else {
        // head precompute; all 256 threads reach barriers, work gated tid<128
        __shared__ float wl[D];
        __shared__ float cpart[D];
        int k = tid;
        if (k < D) wl[k] = Wl[k];
        __syncthreads();
        if (k < D) {
            float s = 0.f;
#pragma unroll 8
            for (int j = 0; j < D; j++) s += W2[k * D + j] * wl[j];
            g_v[k] = s;
            cpart[k] = b2[k] * wl[k];
        }
        __syncthreads();
        for (int st = 64; st; st >>= 1) {
            if (k < st) cpart[k] += cpart[k + st];
            __syncthreads();
        }
        if (k == 0) g_c = cpart[0] + bl[0];
    }
}

// ==== K3 (profiled): agg1 with fp16 (HADD2) accumulation =================
__global__ void agg_bias_relu_z_kernel(const float* __restrict__ b, int n)
{
    int gt = blockIdx.x * blockDim.x + threadIdx.x;
    int row = gt >> 5, lane = gt & 31;
    if (row >= n) return;

    const uint2* h2 = (const uint2*)g_h16;   // 8B = 4 halves per lane

    uint2 u0 = h2[row * 32 + lane];          // self h'
    __half2 acc01 = *(__half2*)&u0.x;
    __half2 acc23 = *(__half2*)&u0.y;

    int end = g_rowptr[row + 1];
    int e = g_rowptr[row];
    for (; e + 7 < end; e += 8) {
        int s[8];
#pragma unroll
        for (int j = 0; j < 8; j++) s[j] = __ldg(&g_csr_src[e + j]);
        uint2 u[8];
#pragma unroll
        for (int j = 0; j < 8; j++) u[j] = h2[s[j] * 32 + lane];
#pragma unroll
        for (int j = 0; j < 8; j++) {
            acc01 = __hadd2(acc01, *(__half2*)&u[j].x);
            acc23 = __hadd2(acc23, *(__half2*)&u[j].y);
        }
    }
    for (; e < end; e++) {
        uint2 u = h2[__ldg(&g_csr_src[e]) * 32 + lane];
        acc01 = __hadd2(acc01, *(__half2*)&u.x);
        acc23 = __hadd2(acc23, *(__half2*)&u.y);
    }

    float2 f01 = __half22float2(acc01);
    float2 f23 = __half22float2(acc23);

    float di = g_dinv[row];
    float4 bb = ((const float4*)b)[lane];
    float a0 = fmaxf(f01.x * di + bb.x, 0.f);
    float a1 = fmaxf(f01.y * di + bb.y, 0.f);
    float a2 = fmaxf(f23.x * di + bb.z, 0.f);
    float a3 = fmaxf(f23.y * di + bb.w, 0.f);

    float4 vv = ((const float4*)g_v)[lane];
    float s = a0 * vv.x + a1 * vv.y + a2 * vv.z + a3 * vv.w;
#pragma unroll
    for (int o = 16; o; o >>= 1) s += __shfl_xor_sync(0xffffffffu, s, o);
    if (lane == 0) g_z[row] = di * s;          // store z' = dinv * z
}

// ==== K4: out = sigmoid(dinv*(z'self + sum z'src) + c); resets scratch ===
__global__ void zagg_kernel(float* __restrict__ out, int n)
{
    int i = blockIdx.x * blockDim.x + threadIdx.x;
    if (i >= n) return;
    g_deg[i] = 0;
    if (i == 0) { g_done = 0; g_flag = 0; }
    float acc = g_z[i];
    int end = g_rowptr[i + 1];
    int e = g_rowptr[i];
    // align to 4 for vector index loads
    for (; e < end && (e & 3); e++)
        acc += g_z[__ldg(&g_csr_src[e])];
    for (; e + 7 < end; e += 8) {
        int4 sa = *(const int4*)&g_csr_src[e];
        int4 sb = *(const int4*)&g_csr_src[e + 4];
        float z0 = g_z[sa.x], z1 = g_z[sa.y], z2 = g_z[sa.z], z3 = g_z[sa.w];
        float z4 = g_z[sb.x], z5 = g_z[sb.y], z6 = g_z[sb.z], z7 = g_z[sb.w];
        acc += ((z0 + z1) + (z2 + z3)) + ((z4 + z5) + (z6 + z7));
    }
    for (; e < end; e++)
        acc += g_z[__ldg(&g_csr_src[e])];
    out[i] = 1.f / (1.f + expf(-(g_dinv[i] * acc + g_c)));
}

// ================= host =================
extern "C" void kernel_launch(void* const* d_in, const int* in_sizes, int n_in,
                              void* d_out, int out_size)
{
    const float* x  = (const float*)d_in[0];
    const void*  ei = d_in[1];
    const float* W1 = (const float*)d_in[2];
    const float* b1 = (const float*)d_in[3];
    const float* W2 = (const float*)d_in[4];
    const float* b2 = (const float*)d_in[5];
    const float* Wl = (const float*)d_in[6];
    const float* bl = (const float*)d_in[7];
    float* out = (float*)d_out;

    const int n = in_sizes[0] / D;   // 50000
    const int E = in_sizes[1] / 2;   // 800000

    const int TB = 256;
    int nb_n     = (n + TB - 1) / TB;        // 196
    int nb_E     = (E + TB - 1) / TB;        // 3125
    int nb_warpN = (n * 32 + TB - 1) / TB;   // 6250

    deg_count_kernel<<<nb_E, TB>>>(ei, E);                           // 0
    scan_dinv_kernel<<<nb_n, TB>>>(n);                               // 1
    mega_kernel<<<GEMM_BLKS + nb_E + 1, TB>>>(x, W1, ei,
                                              W2, b2, Wl, bl,
                                              n, E, nb_E);           // 2
    agg_bias_relu_z_kernel<<<nb_warpN, TB>>>(b1, n);                 // 3 <- profiled
    zagg_kernel<<<nb_n, TB>>>(out, n);                               // 4
}